// round 15
// baseline (speedup 1.0000x reference)
#include <cuda_runtime.h>
#include <cuda_bf16.h>
#include <cstdint>
#include <cstdio>
#include <math.h>

#define NB    16
#define TPH   512
#define TMEL  2048
#define DIMH  256
#define NMELS 80
#define NEGC  (-1e9f)
#define VCONST (-73.5150826563738f)

#define ATTN_N (NB*TPH*TMEL)
#define EXP_N  (NB*TMEL*NMELS)

__device__ int g_dtflag;

// ---- staged float32 copies of all inputs ----
__device__ __align__(16) int   s_ph[NB * TPH];
__device__ __align__(16) float s_mel[NB * TMEL * NMELS];
__device__ __align__(16) float s_emb[512 * DIMH];
__device__ __align__(16) float s_Wih_f[768 * DIMH];
__device__ __align__(16) float s_Whh_f[768 * DIMH];
__device__ __align__(16) float s_Wih_b[768 * DIMH];
__device__ __align__(16) float s_Whh_b[768 * DIMH];
__device__ __align__(16) float s_bih_f[768];
__device__ __align__(16) float s_bhh_f[768];
__device__ __align__(16) float s_bih_b[768];
__device__ __align__(16) float s_bhh_b[768];
__device__ __align__(16) float s_Wfc[NMELS * 512];
__device__ __align__(16) float s_bfc[NMELS];

// ---- scratch ----
__device__ __align__(16) float g_WihT[DIMH * 1536];
__device__ __align__(16) float g_WhhT[2 * DIMH * 768];
__device__ __align__(16) float g_WfcT[2 * DIMH * NMELS];
__device__ __align__(16) float g_xproj[TPH * 1536];
__device__ __align__(16) float g_H[2 * NB * TPH * DIMH];
__device__ __align__(16) float g_xenc[NB * TPH * NMELS];
__device__ __align__(16) float g_musq[NB * TPH];
__device__ __align__(16) float g_ysq[NB * TMEL];
__device__ __align__(16) float g_V[(size_t)NB * TMEL * TPH];
__device__ unsigned g_diag[NB * TMEL * (TPH / 32)];
__device__ int   g_path[NB * TMEL];
__device__ float g_partial[NB * TMEL];

// ---------- XLA-exact tanh / logistic (separate mul/add, no contraction) ----------
__device__ __forceinline__ float xla_tanh(float x) {
    const float kMax = 7.90531110763549805f;
    float cx = fmaxf(-kMax, fminf(x, kMax));
    float x2 = __fmul_rn(cx, cx);
    float p = -2.76076847742355e-16f;
    p = __fadd_rn(__fmul_rn(p, x2), 2.00018790482477e-13f);
    p = __fadd_rn(__fmul_rn(p, x2), -8.60467152213735e-11f);
    p = __fadd_rn(__fmul_rn(p, x2), 5.12229709037114e-08f);
    p = __fadd_rn(__fmul_rn(p, x2), 1.48572235717979e-05f);
    p = __fadd_rn(__fmul_rn(p, x2), 6.37261928875436e-04f);
    p = __fadd_rn(__fmul_rn(p, x2), 4.89352455891786e-03f);
    float np = __fmul_rn(cx, p);
    float q = 1.19825839466702e-06f;
    q = __fadd_rn(__fmul_rn(q, x2), 1.18534705686654e-04f);
    q = __fadd_rn(__fmul_rn(q, x2), 2.26843463243900e-03f);
    q = __fadd_rn(__fmul_rn(q, x2), 4.89352518554385e-03f);
    float t = __fdiv_rn(np, q);
    return (fabsf(x) < 4.0e-4f) ? x : t;
}
__device__ __forceinline__ float xla_sigmoid(float x) {
    float t = xla_tanh(__fmul_rn(x, 0.5f));
    return __fadd_rn(0.5f, __fmul_rn(0.5f, t));
}

// ---------- dtype probe / conversion (proven safe) ----------
__global__ void k_probe(const void* emb, const void* ph) {
    __shared__ int cnt;
    __shared__ int i64ok;
    int t = threadIdx.x;
    if (t == 0) { cnt = 0; i64ok = 1; }
    __syncthreads();
    unsigned short u = ((const unsigned short*)emb)[2 * t];
    int e = (u >> 7) & 0xFF;
    int plaus = (u == 0) || (e >= 90 && e <= 134);
    atomicAdd(&cnt, plaus);
    if (t < 64) {
        int lo = ((const int*)ph)[2 * t];
        int hi = ((const int*)ph)[2 * t + 1];
        if (!(hi == 0 && lo >= 0 && lo < 512)) atomicAnd(&i64ok, 0);
    }
    __syncthreads();
    if (t == 0) {
        int f = 0;
        if (cnt >= 128) f |= 1;
        if (i64ok)      f |= 2;
        g_dtflag = f;
    }
}
__global__ void k_cvt(const void* src, float* dst, int n) {
    int i = blockIdx.x * blockDim.x + threadIdx.x;
    if (i >= n) return;
    if (g_dtflag & 1) dst[i] = __bfloat162float(((const __nv_bfloat16*)src)[i]);
    else              dst[i] = ((const float*)src)[i];
}
__global__ void k_cvt_ph(const void* src) {
    int i = blockIdx.x * blockDim.x + threadIdx.x;
    if (i >= NB * TPH) return;
    int v;
    if (g_dtflag & 2) v = (int)((const long long*)src)[i];
    else              v = ((const int*)src)[i];
    s_ph[i] = v & 511;
}

__device__ __forceinline__ void store_out(void* out, long long idx, long long osz, float v) {
    if (idx < 0 || idx >= osz) return;
    ((float*)out)[idx] = v;
}
__global__ void k_zero(void* out, long long n, long long osz) {
    long long i = (long long)blockIdx.x * blockDim.x + threadIdx.x;
    if (i < n) store_out(out, i, osz, 0.f);
}

__global__ void k_transpose() {
    int j = blockIdx.x;
    int dir = blockIdx.y;
    int which = blockIdx.z;
    int k = threadIdx.x;
    if (which == 0) {
        const float* W = dir ? s_Wih_b : s_Wih_f;
        g_WihT[k * 1536 + dir * 768 + j] = W[j * DIMH + k];
        if (j < NMELS) {
            g_WfcT[(dir * DIMH + k) * NMELS + j] = s_Wfc[j * 512 + dir * DIMH + k];
        }
    } else {
        const float* W = dir ? s_Whh_b : s_Whh_f;
        g_WhhT[(dir * DIMH + k) * 768 + j] = W[j * DIMH + k];
    }
}

// ---------- xproj: dot (sequential k, single acc, fma) THEN + bias ----------
__global__ void k_embproj() {
    int p = blockIdx.x;
    int j = threadIdx.x;
    __shared__ float s_e[DIMH];
    s_e[j] = s_emb[p * DIMH + j];
    __syncthreads();
    float acc[6];
#pragma unroll
    for (int i = 0; i < 6; i++) acc[i] = 0.f;
    for (int k = 0; k < DIMH; k++) {
        float e = s_e[k];
        const float* w = g_WihT + k * 1536;
#pragma unroll
        for (int i = 0; i < 6; i++) acc[i] = fmaf(w[i * 256 + j], e, acc[i]);
    }
#pragma unroll
    for (int i = 0; i < 6; i++) {
        int jj = i * 256 + j;
        float b = (jj < 768) ? s_bih_f[jj] : s_bih_b[jj - 768];
        g_xproj[p * 1536 + jj] = __fadd_rn(acc[i], b);
    }
}

// ---------- GRU: exact XLA op mirroring ----------
__global__ void __launch_bounds__(DIMH) k_gru() {
    int dir = blockIdx.x >> 4, b = blockIdx.x & 15;
    int j = threadIdx.x;
    __shared__ float h_s[DIMH];
    h_s[j] = 0.f;
    const float* Wt = g_WhhT + (size_t)dir * DIMH * 768;
    const float* bhh = dir ? s_bhh_b : s_bhh_f;
    float br = bhh[j], bz = bhh[j + 256], bn = bhh[j + 512];
    const int* phb = s_ph + b * TPH;
    float* Hout = g_H + ((size_t)(dir * NB + b)) * TPH * DIMH;
    __syncthreads();
    for (int s = 0; s < TPH; s++) {
        int t = dir ? (TPH - 1 - s) : s;
        int pv = phb[t] & 511;
        const float* xp = g_xproj + (size_t)pv * 1536 + dir * 768;
        float ar = 0.f, az = 0.f, an = 0.f;
#pragma unroll 8
        for (int k = 0; k < DIMH; k++) {
            float hk = h_s[k];
            const float* w = Wt + k * 768;
            ar = fmaf(w[j], hk, ar);
            az = fmaf(w[j + 256], hk, az);
            an = fmaf(w[j + 512], hk, an);
        }
        float hr = __fadd_rn(ar, br);
        float hz = __fadd_rn(az, bz);
        float hn = __fadd_rn(an, bn);
        float r = xla_sigmoid(__fadd_rn(xp[j], hr));
        float z = xla_sigmoid(__fadd_rn(xp[j + 256], hz));
        float n = xla_tanh(__fadd_rn(xp[j + 512], __fmul_rn(r, hn)));
        float hprev = h_s[j];
        float hnew = __fadd_rn(__fmul_rn(__fsub_rn(1.0f, z), n), __fmul_rn(z, hprev));
        __syncthreads();
        h_s[j] = hnew;
        Hout[(size_t)t * DIMH + j] = hnew;
        __syncthreads();
    }
}

// ---------- fc: dot (sequential k) + bias; musq sequential ----------
__global__ void __launch_bounds__(96) k_fc() {
    int p = blockIdx.x;
    int b = blockIdx.y;
    int m = threadIdx.x;
    __shared__ float hcat[512];
    __shared__ float sq[96];
    for (int d = m; d < 512; d += 96) {
        float v;
        if (d < DIMH) v = g_H[((size_t)b * TPH + p) * DIMH + d];
        else          v = g_H[((size_t)(NB + b) * TPH + p) * DIMH + (d - DIMH)];
        hcat[d] = v;
    }
    __syncthreads();
    float ss = 0.f;
    if (m < NMELS) {
        float acc = 0.f;
        for (int d = 0; d < 512; d++)
            acc = fmaf(g_WfcT[d * NMELS + m], hcat[d], acc);
        acc = __fadd_rn(acc, s_bfc[m]);
        g_xenc[((size_t)b * TPH + p) * NMELS + m] = acc;
        ss = __fmul_rn(acc, acc);
    }
    sq[m] = ss;
    __syncthreads();
    if (m == 0) {
        float s = 0.f;
        for (int k = 0; k < NMELS; k++) s = __fadd_rn(s, sq[k]);
        g_musq[b * TPH + p] = __fmul_rn(-0.5f, s);
    }
}

__global__ void k_ysq() {
    int i = blockIdx.x * blockDim.x + threadIdx.x;
    if (i >= NB * TMEL) return;
    const float* r = s_mel + (size_t)i * NMELS;
    float s = 0.f;
    for (int k = 0; k < NMELS; k++) s = __fadd_rn(s, __fmul_rn(r[k], r[k]));
    g_ysq[i] = __fmul_rn(-0.5f, s);
}

// ---------- V: ((ysq - ymu) + musq) + const, exact association ----------
__global__ void __launch_bounds__(256) k_vgemm() {
    int b = blockIdx.z;
    int y0 = blockIdx.y * 64, p0 = blockIdx.x * 64;
    int t = threadIdx.x;
    int ty = t >> 4, tp = t & 15;
    __shared__ __align__(16) float sm[NMELS][64];
    __shared__ __align__(16) float sx[NMELS][64];
    for (int idx = t; idx < 64 * NMELS; idx += 256) {
        int i = idx / NMELS, k = idx % NMELS;
        sm[k][i] = s_mel[((size_t)b * TMEL + y0 + i) * NMELS + k];
        sx[k][i] = g_xenc[((size_t)b * TPH + p0 + i) * NMELS + k];
    }
    __syncthreads();
    float acc[4][4];
#pragma unroll
    for (int i = 0; i < 4; i++)
#pragma unroll
        for (int jj = 0; jj < 4; jj++) acc[i][jj] = 0.f;
    for (int k = 0; k < NMELS; k++) {
        float4 a = ((const float4*)&sm[k][0])[ty];
        float4 bb = ((const float4*)&sx[k][0])[tp];
        float av[4] = {a.x, a.y, a.z, a.w};
        float bv[4] = {bb.x, bb.y, bb.z, bb.w};
#pragma unroll
        for (int i = 0; i < 4; i++)
#pragma unroll
            for (int jj = 0; jj < 4; jj++) acc[i][jj] = fmaf(av[i], bv[jj], acc[i][jj]);
    }
    float4 mu = ((const float4*)(g_musq + b * TPH + p0))[tp];
    float muv[4] = {mu.x, mu.y, mu.z, mu.w};
#pragma unroll
    for (int i = 0; i < 4; i++) {
        int y = y0 + ty * 4 + i;
        float ys = g_ysq[b * TMEL + y];
        float4 o;
#pragma unroll
        for (int jj = 0; jj < 4; jj++) {
            // ymu = -acc (exact by sign symmetry); v = ((ys - ymu) + mu) + C
            float v1 = __fadd_rn(ys, acc[i][jj]);
            float v2 = __fadd_rn(v1, muv[jj]);
            float vv = __fadd_rn(v2, VCONST);
            if (jj == 0) o.x = vv; else if (jj == 1) o.y = vv;
            else if (jj == 2) o.z = vv; else o.w = vv;
        }
        ((float4*)(g_V + ((size_t)b * TMEL + y) * TPH + p0))[tp] = o;
    }
}

__global__ void __launch_bounds__(TPH) k_dp() {
    int b = blockIdx.x, x = threadIdx.x;
    __shared__ float s_c[TPH];
    float carry = (x == 0) ? 0.f : NEGC;
    const float* Vb = g_V + (size_t)b * TMEL * TPH;
    float v = Vb[x];
    for (int y = 0; y < TMEL; y++) {
        float vnext = (y + 1 < TMEL) ? Vb[(size_t)(y + 1) * TPH + x] : 0.f;
        s_c[x] = carry;
        __syncthreads();
        float sh = (x > 0) ? s_c[x - 1] : NEGC;
        unsigned bal = __ballot_sync(0xffffffffu, sh > carry);
        if ((x & 31) == 0) g_diag[(b * TMEL + y) * 16 + (x >> 5)] = bal;
        carry = __fadd_rn(v, fmaxf(carry, sh));
        v = vnext;
        __syncthreads();
    }
}

__global__ void k_backtrack() {
    __shared__ unsigned s_d[256 * 16];
    __shared__ int s_idx;
    int b = blockIdx.x, t = threadIdx.x;
    if (t == 0) s_idx = TPH - 1;
    for (int chunk = 7; chunk >= 0; chunk--) {
        __syncthreads();
        const unsigned* src = g_diag + ((size_t)b * TMEL + chunk * 256) * 16;
        for (int i = t; i < 256 * 16; i += blockDim.x) s_d[i] = src[i];
        __syncthreads();
        if (t == 0) {
            int idx = s_idx;
            for (int yy = 255; yy >= 0; yy--) {
                g_path[b * TMEL + chunk * 256 + yy] = idx;
                int bit = (s_d[yy * 16 + ((idx >> 5) & 15)] >> (idx & 31)) & 1;
                idx -= bit;
                if (idx < 0) idx = 0;
            }
            s_idx = idx;
        }
    }
}

__global__ void k_finish(void* out, long long osz) {
    int y = blockIdx.x, b = blockIdx.y;
    int m = threadIdx.x;
    int p = g_path[b * TMEL + y] & 511;
    if (m == 0) {
        store_out(out, (long long)(b * TPH + p) * TMEL + y, osz, 1.f);
    }
    float sq = 0.f;
    if (m < NMELS) {
        float e = g_xenc[((size_t)b * TPH + p) * NMELS + m];
        store_out(out, (long long)ATTN_N + (long long)(b * TMEL + y) * NMELS + m, osz, e);
        float d = e - s_mel[((size_t)b * TMEL + y) * NMELS + m];
        sq = d * d;
    }
#pragma unroll
    for (int off = 16; off > 0; off >>= 1) sq += __shfl_down_sync(0xffffffffu, sq, off);
    __shared__ float s_w[3];
    if ((m & 31) == 0) s_w[m >> 5] = sq;
    __syncthreads();
    if (m == 0) g_partial[b * TMEL + y] = s_w[0] + s_w[1] + s_w[2];
}

__global__ void k_loss(void* out, long long osz) {
    __shared__ double s[512];
    int t = threadIdx.x;
    double acc = 0.0;
    for (int i = 0; i < 64; i++) acc += (double)g_partial[t * 64 + i];
    s[t] = acc;
    __syncthreads();
    for (int off = 256; off > 0; off >>= 1) {
        if (t < off) s[t] += s[t + off];
        __syncthreads();
    }
    if (t == 0) store_out(out, (long long)ATTN_N + (long long)EXP_N, osz,
                          (float)(s[0] / 32768.0 / 80.0));
}

// ---------- host ----------
template <typename T>
static float* symaddr(T& s) {
    void* p = 0;
    cudaGetSymbolAddress(&p, s);
    return (float*)p;
}
static void dbg_sync(const char* name) {
    cudaStreamCaptureStatus st = cudaStreamCaptureStatusNone;
    cudaStreamIsCapturing(0, &st);
    if (st != cudaStreamCaptureStatusNone) return;
    cudaError_t e = cudaDeviceSynchronize();
    fprintf(stderr, "[ck] %s: %s\n", name, cudaGetErrorName(e));
    fflush(stderr);
}

extern "C" void kernel_launch(void* const* d_in, const int* in_sizes, int n_in,
                              void* d_out, int out_size) {
    const void* ph = 0;
    const void *mel = 0, *emb = 0, *Wfc = 0, *bfc = 0;
    const void* W196[4] = {0, 0, 0, 0};
    const void* b768[4] = {0, 0, 0, 0};
    int n196 = 0, n768 = 0;
    for (int i = 0; i < n_in; i++) {
        int sz = in_sizes[i];
        if (sz == NB * TPH && !ph)                ph  = d_in[i];
        else if (sz == NB * TMEL * NMELS && !mel) mel = d_in[i];
        else if (sz == 512 * DIMH && !emb)        emb = d_in[i];
        else if (sz == 768 * DIMH && n196 < 4)    W196[n196++] = d_in[i];
        else if (sz == 768 && n768 < 4)           b768[n768++] = d_in[i];
        else if (sz == NMELS * 512 && !Wfc)       Wfc = d_in[i];
        else if (sz == NMELS && !bfc)             bfc = d_in[i];
    }
    long long osz = (long long)out_size;

    k_probe<<<1, 256>>>(emb, ph);

    struct { const void* src; float* dst; int n; } cv[11] = {
        {mel,     symaddr(s_mel),   NB * TMEL * NMELS},
        {emb,     symaddr(s_emb),   512 * DIMH},
        {W196[0], symaddr(s_Wih_f), 768 * DIMH},
        {W196[1], symaddr(s_Whh_f), 768 * DIMH},
        {W196[2], symaddr(s_Wih_b), 768 * DIMH},
        {W196[3], symaddr(s_Whh_b), 768 * DIMH},
        {b768[0], symaddr(s_bih_f), 768},
        {b768[1], symaddr(s_bhh_f), 768},
        {b768[2], symaddr(s_bih_b), 768},
        {b768[3], symaddr(s_bhh_b), 768},
        {Wfc,     symaddr(s_Wfc),   NMELS * 512},
    };
    for (int i = 0; i < 11; i++)
        if (cv[i].src && cv[i].dst)
            k_cvt<<<(cv[i].n + 255) / 256, 256>>>(cv[i].src, cv[i].dst, cv[i].n);
    k_cvt<<<1, NMELS>>>(bfc, symaddr(s_bfc), NMELS);
    k_cvt_ph<<<(NB * TPH + 255) / 256, 256>>>(ph);
    dbg_sync("cvt");

    k_transpose<<<dim3(768, 2, 2), 256>>>();
    k_embproj<<<TPH, 256>>>();
    dbg_sync("embproj");
    k_gru<<<32, DIMH>>>();
    dbg_sync("gru");
    k_fc<<<dim3(TPH, NB), 96>>>();
    k_ysq<<<(NB * TMEL + 255) / 256, 256>>>();
    k_vgemm<<<dim3(TPH / 64, TMEL / 64, NB), 256>>>();
    dbg_sync("vgemm");
    k_dp<<<NB, TPH>>>();
    k_backtrack<<<NB, 256>>>();
    dbg_sync("dp+bt");

    long long zn = osz < (long long)ATTN_N ? osz : (long long)ATTN_N;
    k_zero<<<(int)((zn + 255) / 256), 256>>>(d_out, zn, osz);
    k_finish<<<dim3(TMEL, NB), 96>>>(d_out, osz);
    k_loss<<<1, 512>>>(d_out, osz);
    dbg_sync("out");
}

// round 16
// speedup vs baseline: 6.3034x; 6.3034x over previous
#include <cuda_runtime.h>
#include <cuda_bf16.h>
#include <cstdint>
#include <cstdio>
#include <math.h>

#define NB    16
#define TPH   512
#define TMEL  2048
#define DIMH  256
#define NMELS 80
#define NEGC  (-1e9f)
#define VCONST (-73.5150826563738f)

#define ATTN_N (NB*TPH*TMEL)
#define EXP_N  (NB*TMEL*NMELS)

__device__ int g_dtflag;

// ---- staged float32 copies of all inputs ----
__device__ __align__(16) int   s_ph[NB * TPH];
__device__ __align__(16) float s_mel[NB * TMEL * NMELS];
__device__ __align__(16) float s_emb[512 * DIMH];
__device__ __align__(16) float s_Wih_f[768 * DIMH];
__device__ __align__(16) float s_Whh_f[768 * DIMH];
__device__ __align__(16) float s_Wih_b[768 * DIMH];
__device__ __align__(16) float s_Whh_b[768 * DIMH];
__device__ __align__(16) float s_bih_f[768];
__device__ __align__(16) float s_bhh_f[768];
__device__ __align__(16) float s_bih_b[768];
__device__ __align__(16) float s_bhh_b[768];
__device__ __align__(16) float s_Wfc[NMELS * 512];
__device__ __align__(16) float s_bfc[NMELS];

// ---- scratch ----
__device__ __align__(16) float g_WihT[DIMH * 1536];
__device__ __align__(16) float g_WhhT[2 * DIMH * 768];
__device__ __align__(16) float g_WfcT[2 * DIMH * NMELS];
__device__ __align__(16) float g_xproj[TPH * 1536];
__device__ __align__(16) float g_H[2 * NB * TPH * DIMH];
__device__ __align__(16) float g_xenc[NB * TPH * NMELS];
__device__ __align__(16) float g_musq[NB * TPH];
__device__ __align__(16) float g_ysq[NB * TMEL];
__device__ __align__(16) float g_V[(size_t)NB * TMEL * TPH];
__device__ unsigned g_diag[NB * TMEL * (TPH / 32)];
__device__ int   g_path[NB * TMEL];
__device__ float g_partial[NB * TMEL];

// ---------- XLA-exact tanh / logistic ----------
__device__ __forceinline__ float xla_tanh(float x) {
    const float kMax = 7.90531110763549805f;
    float cx = fmaxf(-kMax, fminf(x, kMax));
    float x2 = __fmul_rn(cx, cx);
    float p = -2.76076847742355e-16f;
    p = __fadd_rn(__fmul_rn(p, x2), 2.00018790482477e-13f);
    p = __fadd_rn(__fmul_rn(p, x2), -8.60467152213735e-11f);
    p = __fadd_rn(__fmul_rn(p, x2), 5.12229709037114e-08f);
    p = __fadd_rn(__fmul_rn(p, x2), 1.48572235717979e-05f);
    p = __fadd_rn(__fmul_rn(p, x2), 6.37261928875436e-04f);
    p = __fadd_rn(__fmul_rn(p, x2), 4.89352455891786e-03f);
    float np = __fmul_rn(cx, p);
    float q = 1.19825839466702e-06f;
    q = __fadd_rn(__fmul_rn(q, x2), 1.18534705686654e-04f);
    q = __fadd_rn(__fmul_rn(q, x2), 2.26843463243900e-03f);
    q = __fadd_rn(__fmul_rn(q, x2), 4.89352518554385e-03f);
    float t = __fdiv_rn(np, q);
    return (fabsf(x) < 4.0e-4f) ? x : t;
}
__device__ __forceinline__ float xla_sigmoid(float x) {
    float t = xla_tanh(__fmul_rn(x, 0.5f));
    return __fadd_rn(0.5f, __fmul_rn(0.5f, t));
}

// ---------- cluster helpers ----------
__device__ __forceinline__ unsigned ctarank() {
    unsigned r; asm("mov.u32 %0, %%cluster_ctarank;" : "=r"(r)); return r;
}
__device__ __forceinline__ unsigned smem_addr_u32(const void* p) {
    return (unsigned)__cvta_generic_to_shared(p);
}
__device__ __forceinline__ void st_cluster_f32(unsigned saddr, unsigned rank, float v) {
    asm volatile(
        "{\n\t.reg .b32 ra;\n\t"
        "mapa.shared::cluster.u32 ra, %0, %1;\n\t"
        "st.shared::cluster.f32 [ra], %2;\n\t}"
        :: "r"(saddr), "r"(rank), "f"(v) : "memory");
}
#define CLUSTER_SYNC() do { \
    asm volatile("barrier.cluster.arrive.aligned;" ::: "memory"); \
    asm volatile("barrier.cluster.wait.aligned;" ::: "memory"); } while (0)

// ---------- dtype probe ----------
__global__ void k_probe(const void* emb, const void* ph) {
    __shared__ int cnt;
    __shared__ int i64ok;
    int t = threadIdx.x;
    if (t == 0) { cnt = 0; i64ok = 1; }
    __syncthreads();
    unsigned short u = ((const unsigned short*)emb)[2 * t];
    int e = (u >> 7) & 0xFF;
    int plaus = (u == 0) || (e >= 90 && e <= 134);
    atomicAdd(&cnt, plaus);
    if (t < 64) {
        int lo = ((const int*)ph)[2 * t];
        int hi = ((const int*)ph)[2 * t + 1];
        if (!(hi == 0 && lo >= 0 && lo < 512)) atomicAnd(&i64ok, 0);
    }
    __syncthreads();
    if (t == 0) {
        int f = 0;
        if (cnt >= 128) f |= 1;
        if (i64ok)      f |= 2;
        g_dtflag = f;
    }
}

// ---------- single conversion kernel (all 13 inputs) ----------
__global__ void k_cvt_all(const void* mel, const void* emb,
                          const void* w0, const void* w1, const void* w2, const void* w3,
                          const void* b0, const void* b1, const void* b2, const void* b3,
                          const void* wfc, const void* bfc, const void* ph) {
    int i = blockIdx.x * 256 + threadIdx.x;
    int seg = blockIdx.y;
    if (seg == 12) {
        if (i < NB * TPH) {
            int v;
            if (g_dtflag & 2) v = (int)((const long long*)ph)[i];
            else              v = ((const int*)ph)[i];
            s_ph[i] = v & 511;
        }
        return;
    }
    const void* src = 0; float* dst = 0; int n = 0;
    switch (seg) {
        case 0:  src = mel; dst = s_mel;   n = NB * TMEL * NMELS; break;
        case 1:  src = emb; dst = s_emb;   n = 512 * DIMH; break;
        case 2:  src = w0;  dst = s_Wih_f; n = 768 * DIMH; break;
        case 3:  src = w1;  dst = s_Whh_f; n = 768 * DIMH; break;
        case 4:  src = w2;  dst = s_Wih_b; n = 768 * DIMH; break;
        case 5:  src = w3;  dst = s_Whh_b; n = 768 * DIMH; break;
        case 6:  src = b0;  dst = s_bih_f; n = 768; break;
        case 7:  src = b1;  dst = s_bhh_f; n = 768; break;
        case 8:  src = b2;  dst = s_bih_b; n = 768; break;
        case 9:  src = b3;  dst = s_bhh_b; n = 768; break;
        case 10: src = wfc; dst = s_Wfc;   n = NMELS * 512; break;
        default: src = bfc; dst = s_bfc;   n = NMELS; break;
    }
    if (i < n) {
        if (g_dtflag & 1) dst[i] = __bfloat162float(((const __nv_bfloat16*)src)[i]);
        else              dst[i] = ((const float*)src)[i];
    }
}

__device__ __forceinline__ void store_out(void* out, long long idx, long long osz, float v) {
    if (idx < 0 || idx >= osz) return;
    ((float*)out)[idx] = v;
}
__global__ void k_zero(void* out, long long n, long long osz) {
    long long i = (long long)blockIdx.x * blockDim.x + threadIdx.x;
    if (i < n) store_out(out, i, osz, 0.f);
}

__global__ void k_transpose() {
    int j = blockIdx.x;
    int dir = blockIdx.y;
    int which = blockIdx.z;
    int k = threadIdx.x;
    if (which == 0) {
        const float* W = dir ? s_Wih_b : s_Wih_f;
        g_WihT[k * 1536 + dir * 768 + j] = W[j * DIMH + k];
        if (j < NMELS) {
            g_WfcT[(dir * DIMH + k) * NMELS + j] = s_Wfc[j * 512 + dir * DIMH + k];
        }
    } else {
        const float* W = dir ? s_Whh_b : s_Whh_f;
        g_WhhT[(dir * DIMH + k) * 768 + j] = W[j * DIMH + k];
    }
}

// ---------- xproj ----------
__global__ void k_embproj() {
    int p = blockIdx.x;
    int j = threadIdx.x;
    __shared__ float s_e[DIMH];
    s_e[j] = s_emb[p * DIMH + j];
    __syncthreads();
    float acc[6];
#pragma unroll
    for (int i = 0; i < 6; i++) acc[i] = 0.f;
    for (int k = 0; k < DIMH; k++) {
        float e = s_e[k];
        const float* w = g_WihT + k * 1536;
#pragma unroll
        for (int i = 0; i < 6; i++) acc[i] = fmaf(w[i * 256 + j], e, acc[i]);
    }
#pragma unroll
    for (int i = 0; i < 6; i++) {
        int jj = i * 256 + j;
        float b = (jj < 768) ? s_bih_f[jj] : s_bih_b[jj - 768];
        g_xproj[p * 1536 + jj] = __fadd_rn(acc[i], b);
    }
}

// ---------- GRU: 4-CTA cluster, SMEM-resident Whh slice, DSMEM h-broadcast ----------
// Per cluster = one (dir,b). CTA rank owns h-dims [rank*64, rank*64+64).
// Thread tid (0..191): gate g = tid/64, l = tid%64, row = g*256 + rank*64 + l.
// Whh slice stored quad-k: wq[(q*192 + tid)*4 + c] = WhhT[(4q+c)*768 + row].
// Dot is sequential ascending k with single-accumulator fmaf => bit-identical.
#define GRU_SMEM_BYTES ((256*192 + 2*256 + 192 + 192) * 4)
__global__ void __launch_bounds__(192, 1) __cluster_dims__(4, 1, 1) k_gru_cl() {
    extern __shared__ float smf[];
    float* w  = smf;                 // 196608 B
    float* hb = smf + 256 * 192;     // [2][256]
    float* sa = hb + 512;            // [192]
    float* sx = sa + 192;            // [192]
    int tid = threadIdx.x;
    unsigned rk = ctarank();
    int cid = blockIdx.x >> 2;
    int dir = cid >> 4, b = cid & 15;
    int l = tid & 63;
    int row = (tid / 64) * 256 + (int)rk * 64 + l;
    int hd = (int)rk * 64 + l;

    const float* Wt = g_WhhT + (size_t)dir * DIMH * 768;
    for (int q = 0; q < 64; q++) {
        float4 wv;
        wv.x = Wt[(4 * q + 0) * 768 + row];
        wv.y = Wt[(4 * q + 1) * 768 + row];
        wv.z = Wt[(4 * q + 2) * 768 + row];
        wv.w = Wt[(4 * q + 3) * 768 + row];
        ((float4*)w)[q * 192 + tid] = wv;
    }
    for (int k = tid; k < 512; k += 192) hb[k] = 0.f;

    const float* bhh = dir ? s_bhh_b : s_bhh_f;
    float br = 0.f, bz = 0.f, bn = 0.f;
    if (tid < 64) { br = bhh[hd]; bz = bhh[256 + hd]; bn = bhh[512 + hd]; }
    const int* phb = s_ph + b * TPH;
    float* Hout = g_H + ((size_t)(dir * NB + b)) * TPH * DIMH;
    unsigned hb_base = smem_addr_u32(hb);
    __syncthreads();
    CLUSTER_SYNC();

    for (int s = 0; s < TPH; s++) {
        int t = dir ? (TPH - 1 - s) : s;
        int pv = phb[t] & 511;
        float xg = g_xproj[(size_t)pv * 1536 + dir * 768 + row];
        const float* hc = hb + (s & 1) * 256;
        float a = 0.f;
#pragma unroll 8
        for (int q = 0; q < 64; q++) {
            float4 wv = ((const float4*)w)[q * 192 + tid];
            float4 hv = ((const float4*)hc)[q];
            a = fmaf(wv.x, hv.x, a);
            a = fmaf(wv.y, hv.y, a);
            a = fmaf(wv.z, hv.z, a);
            a = fmaf(wv.w, hv.w, a);
        }
        sa[tid] = a;
        sx[tid] = xg;
        __syncthreads();
        if (tid < 64) {
            float hr = __fadd_rn(sa[l], br);
            float hz = __fadd_rn(sa[64 + l], bz);
            float hn = __fadd_rn(sa[128 + l], bn);
            float r = xla_sigmoid(__fadd_rn(sx[l], hr));
            float z = xla_sigmoid(__fadd_rn(sx[64 + l], hz));
            float n = xla_tanh(__fadd_rn(sx[128 + l], __fmul_rn(r, hn)));
            float hprev = hc[hd];
            float hnew = __fadd_rn(__fmul_rn(__fsub_rn(1.0f, z), n), __fmul_rn(z, hprev));
            Hout[(size_t)t * DIMH + hd] = hnew;
            unsigned dst = hb_base + (unsigned)((((s + 1) & 1) * 256 + hd) * 4);
            st_cluster_f32(dst, 0, hnew);
            st_cluster_f32(dst, 1, hnew);
            st_cluster_f32(dst, 2, hnew);
            st_cluster_f32(dst, 3, hnew);
        }
        CLUSTER_SYNC();
    }
}

// ---------- fc ----------
__global__ void __launch_bounds__(96) k_fc() {
    int p = blockIdx.x;
    int b = blockIdx.y;
    int m = threadIdx.x;
    __shared__ float hcat[512];
    __shared__ float sq[96];
    for (int d = m; d < 512; d += 96) {
        float v;
        if (d < DIMH) v = g_H[((size_t)b * TPH + p) * DIMH + d];
        else          v = g_H[((size_t)(NB + b) * TPH + p) * DIMH + (d - DIMH)];
        hcat[d] = v;
    }
    __syncthreads();
    float ss = 0.f;
    if (m < NMELS) {
        float acc = 0.f;
        for (int d = 0; d < 512; d++)
            acc = fmaf(g_WfcT[d * NMELS + m], hcat[d], acc);
        acc = __fadd_rn(acc, s_bfc[m]);
        g_xenc[((size_t)b * TPH + p) * NMELS + m] = acc;
        ss = __fmul_rn(acc, acc);
    }
    sq[m] = ss;
    __syncthreads();
    if (m == 0) {
        float s = 0.f;
        for (int k = 0; k < NMELS; k++) s = __fadd_rn(s, sq[k]);
        g_musq[b * TPH + p] = __fmul_rn(-0.5f, s);
    }
}

__global__ void k_ysq() {
    int i = blockIdx.x * blockDim.x + threadIdx.x;
    if (i >= NB * TMEL) return;
    const float* r = s_mel + (size_t)i * NMELS;
    float s = 0.f;
    for (int k = 0; k < NMELS; k++) s = __fadd_rn(s, __fmul_rn(r[k], r[k]));
    g_ysq[i] = __fmul_rn(-0.5f, s);
}

// ---------- V gemm ----------
__global__ void __launch_bounds__(256) k_vgemm() {
    int b = blockIdx.z;
    int y0 = blockIdx.y * 64, p0 = blockIdx.x * 64;
    int t = threadIdx.x;
    int ty = t >> 4, tp = t & 15;
    __shared__ __align__(16) float sm[NMELS][64];
    __shared__ __align__(16) float sx[NMELS][64];
    for (int idx = t; idx < 64 * NMELS; idx += 256) {
        int i = idx / NMELS, k = idx % NMELS;
        sm[k][i] = s_mel[((size_t)b * TMEL + y0 + i) * NMELS + k];
        sx[k][i] = g_xenc[((size_t)b * TPH + p0 + i) * NMELS + k];
    }
    __syncthreads();
    float acc[4][4];
#pragma unroll
    for (int i = 0; i < 4; i++)
#pragma unroll
        for (int jj = 0; jj < 4; jj++) acc[i][jj] = 0.f;
    for (int k = 0; k < NMELS; k++) {
        float4 a = ((const float4*)&sm[k][0])[ty];
        float4 bb = ((const float4*)&sx[k][0])[tp];
        float av[4] = {a.x, a.y, a.z, a.w};
        float bv[4] = {bb.x, bb.y, bb.z, bb.w};
#pragma unroll
        for (int i = 0; i < 4; i++)
#pragma unroll
            for (int jj = 0; jj < 4; jj++) acc[i][jj] = fmaf(av[i], bv[jj], acc[i][jj]);
    }
    float4 mu = ((const float4*)(g_musq + b * TPH + p0))[tp];
    float muv[4] = {mu.x, mu.y, mu.z, mu.w};
#pragma unroll
    for (int i = 0; i < 4; i++) {
        int y = y0 + ty * 4 + i;
        float ys = g_ysq[b * TMEL + y];
        float4 o;
#pragma unroll
        for (int jj = 0; jj < 4; jj++) {
            float v1 = __fadd_rn(ys, acc[i][jj]);
            float v2 = __fadd_rn(v1, muv[jj]);
            float vv = __fadd_rn(v2, VCONST);
            if (jj == 0) o.x = vv; else if (jj == 1) o.y = vv;
            else if (jj == 2) o.z = vv; else o.w = vv;
        }
        ((float4*)(g_V + ((size_t)b * TMEL + y) * TPH + p0))[tp] = o;
    }
}

// ---------- DP forward: 1 barrier/step, distance-2 prefetch ----------
__global__ void __launch_bounds__(TPH) k_dp() {
    int b = blockIdx.x, x = threadIdx.x;
    __shared__ float s_c[2][TPH];
    float carry = (x == 0) ? 0.f : NEGC;
    const float* Vb = g_V + (size_t)b * TMEL * TPH;
    float v0 = Vb[x];
    float v1 = Vb[TPH + x];
    for (int y = 0; y < TMEL; y++) {
        float vf = (y + 2 < TMEL) ? Vb[(size_t)(y + 2) * TPH + x] : 0.f;
        s_c[y & 1][x] = carry;
        __syncthreads();
        float sh = (x > 0) ? s_c[y & 1][x - 1] : NEGC;
        unsigned bal = __ballot_sync(0xffffffffu, sh > carry);
        if ((x & 31) == 0) g_diag[(b * TMEL + y) * 16 + (x >> 5)] = bal;
        carry = __fadd_rn(v0, fmaxf(carry, sh));
        v0 = v1;
        v1 = vf;
    }
}

__global__ void k_backtrack() {
    __shared__ unsigned s_d[256 * 16];
    __shared__ int s_idx;
    int b = blockIdx.x, t = threadIdx.x;
    if (t == 0) s_idx = TPH - 1;
    for (int chunk = 7; chunk >= 0; chunk--) {
        __syncthreads();
        const unsigned* src = g_diag + ((size_t)b * TMEL + chunk * 256) * 16;
        for (int i = t; i < 256 * 16; i += blockDim.x) s_d[i] = src[i];
        __syncthreads();
        if (t == 0) {
            int idx = s_idx;
            for (int yy = 255; yy >= 0; yy--) {
                g_path[b * TMEL + chunk * 256 + yy] = idx;
                int bit = (s_d[yy * 16 + ((idx >> 5) & 15)] >> (idx & 31)) & 1;
                idx -= bit;
                if (idx < 0) idx = 0;
            }
            s_idx = idx;
        }
    }
}

__global__ void k_finish(void* out, long long osz) {
    int y = blockIdx.x, b = blockIdx.y;
    int m = threadIdx.x;
    int p = g_path[b * TMEL + y] & 511;
    if (m == 0) {
        store_out(out, (long long)(b * TPH + p) * TMEL + y, osz, 1.f);
    }
    float sq = 0.f;
    if (m < NMELS) {
        float e = g_xenc[((size_t)b * TPH + p) * NMELS + m];
        store_out(out, (long long)ATTN_N + (long long)(b * TMEL + y) * NMELS + m, osz, e);
        float d = e - s_mel[((size_t)b * TMEL + y) * NMELS + m];
        sq = d * d;
    }
#pragma unroll
    for (int off = 16; off > 0; off >>= 1) sq += __shfl_down_sync(0xffffffffu, sq, off);
    __shared__ float s_w[3];
    if ((m & 31) == 0) s_w[m >> 5] = sq;
    __syncthreads();
    if (m == 0) g_partial[b * TMEL + y] = s_w[0] + s_w[1] + s_w[2];
}

__global__ void k_loss(void* out, long long osz) {
    __shared__ double s[512];
    int t = threadIdx.x;
    double acc = 0.0;
    for (int i = 0; i < 64; i++) acc += (double)g_partial[t * 64 + i];
    s[t] = acc;
    __syncthreads();
    for (int off = 256; off > 0; off >>= 1) {
        if (t < off) s[t] += s[t + off];
        __syncthreads();
    }
    if (t == 0) store_out(out, (long long)ATTN_N + (long long)EXP_N, osz,
                          (float)(s[0] / 32768.0 / 80.0));
}

// ---------- host ----------
static void dbg_sync(const char* name) {
    cudaStreamCaptureStatus st = cudaStreamCaptureStatusNone;
    cudaStreamIsCapturing(0, &st);
    if (st != cudaStreamCaptureStatusNone) return;
    cudaError_t e = cudaDeviceSynchronize();
    fprintf(stderr, "[ck] %s: %s\n", name, cudaGetErrorName(e));
    fflush(stderr);
}

extern "C" void kernel_launch(void* const* d_in, const int* in_sizes, int n_in,
                              void* d_out, int out_size) {
    const void* ph = 0;
    const void *mel = 0, *emb = 0, *Wfc = 0, *bfc = 0;
    const void* W196[4] = {0, 0, 0, 0};
    const void* b768[4] = {0, 0, 0, 0};
    int n196 = 0, n768 = 0;
    for (int i = 0; i < n_in; i++) {
        int sz = in_sizes[i];
        if (sz == NB * TPH && !ph)                ph  = d_in[i];
        else if (sz == NB * TMEL * NMELS && !mel) mel = d_in[i];
        else if (sz == 512 * DIMH && !emb)        emb = d_in[i];
        else if (sz == 768 * DIMH && n196 < 4)    W196[n196++] = d_in[i];
        else if (sz == 768 && n768 < 4)           b768[n768++] = d_in[i];
        else if (sz == NMELS * 512 && !Wfc)       Wfc = d_in[i];
        else if (sz == NMELS && !bfc)             bfc = d_in[i];
    }
    long long osz = (long long)out_size;

    // launch order chosen so process-launch #6 (ncu -s 5 -c 1) = k_gru_cl
    k_probe<<<1, 256>>>(emb, ph);                                          // 1
    k_cvt_all<<<dim3((NB * TMEL * NMELS + 255) / 256, 13), 256>>>(         // 2
        mel, emb, W196[0], W196[1], W196[2], W196[3],
        b768[0], b768[1], b768[2], b768[3], Wfc, bfc, ph);
    k_transpose<<<dim3(768, 2, 2), 256>>>();                               // 3
    k_embproj<<<TPH, 256>>>();                                             // 4
    long long zn = osz < (long long)ATTN_N ? osz : (long long)ATTN_N;
    k_zero<<<(int)((zn + 255) / 256), 256>>>(d_out, zn, osz);              // 5

    cudaFuncSetAttribute(k_gru_cl, cudaFuncAttributeMaxDynamicSharedMemorySize,
                         GRU_SMEM_BYTES);
    k_gru_cl<<<128, 192, GRU_SMEM_BYTES>>>();                              // 6  <- profiled
    dbg_sync("gru");

    k_fc<<<dim3(TPH, NB), 96>>>();                                         // 7
    k_ysq<<<(NB * TMEL + 255) / 256, 256>>>();                             // 8
    k_vgemm<<<dim3(TPH / 64, TMEL / 64, NB), 256>>>();                     // 9
    k_dp<<<NB, TPH>>>();                                                   // 10
    k_backtrack<<<NB, 256>>>();                                            // 11
    k_finish<<<dim3(TMEL, NB), 96>>>(d_out, osz);                          // 12
    k_loss<<<1, 512>>>(d_out, osz);                                        // 13
    dbg_sync("end");
}

// round 17
// speedup vs baseline: 7.1453x; 1.1336x over previous
#include <cuda_runtime.h>
#include <cuda_bf16.h>
#include <cstdint>
#include <cstdio>
#include <math.h>

#define NB    16
#define TPH   512
#define TMEL  2048
#define DIMH  256
#define NMELS 80
#define NEGC  (-1e9f)
#define VCONST (-73.5150826563738f)

#define ATTN_N (NB*TPH*TMEL)
#define EXP_N  (NB*TMEL*NMELS)

__device__ int g_dtflag;

// ---- staged float32 inputs (only what's still consumed raw) ----
__device__ __align__(16) int   s_ph[NB * TPH];
__device__ __align__(16) float s_mel[NB * TMEL * NMELS];
__device__ __align__(16) float s_emb[512 * DIMH];
__device__ __align__(16) float s_bih_f[768];
__device__ __align__(16) float s_bhh_f[768];
__device__ __align__(16) float s_bih_b[768];
__device__ __align__(16) float s_bhh_b[768];
__device__ __align__(16) float s_bfc[NMELS];

// ---- scratch ----
__device__ __align__(16) float g_WihT[DIMH * 1536];     // [k][1536]
__device__ __align__(16) float g_WhhT[2 * DIMH * 768];  // [(dir*256+k)][768]
__device__ __align__(16) float g_WfcT[512 * NMELS];     // [d][80]
__device__ __align__(16) float g_xproj[TPH * 1536];
__device__ __align__(16) float g_H[2 * NB * TPH * DIMH];
__device__ __align__(16) float g_xenc[NB * TPH * NMELS];
__device__ __align__(16) float g_musq[NB * TPH];
__device__ __align__(16) float g_ysq[NB * TMEL];
__device__ __align__(16) float g_V[(size_t)NB * TMEL * TPH];
__device__ unsigned g_diag[NB * TMEL * (TPH / 32)];
__device__ int   g_path[NB * TMEL];
__device__ float g_partial[NB * TMEL];

// ---------- XLA-exact tanh / logistic ----------
__device__ __forceinline__ float xla_tanh(float x) {
    const float kMax = 7.90531110763549805f;
    float cx = fmaxf(-kMax, fminf(x, kMax));
    float x2 = __fmul_rn(cx, cx);
    float p = -2.76076847742355e-16f;
    p = __fadd_rn(__fmul_rn(p, x2), 2.00018790482477e-13f);
    p = __fadd_rn(__fmul_rn(p, x2), -8.60467152213735e-11f);
    p = __fadd_rn(__fmul_rn(p, x2), 5.12229709037114e-08f);
    p = __fadd_rn(__fmul_rn(p, x2), 1.48572235717979e-05f);
    p = __fadd_rn(__fmul_rn(p, x2), 6.37261928875436e-04f);
    p = __fadd_rn(__fmul_rn(p, x2), 4.89352455891786e-03f);
    float np = __fmul_rn(cx, p);
    float q = 1.19825839466702e-06f;
    q = __fadd_rn(__fmul_rn(q, x2), 1.18534705686654e-04f);
    q = __fadd_rn(__fmul_rn(q, x2), 2.26843463243900e-03f);
    q = __fadd_rn(__fmul_rn(q, x2), 4.89352518554385e-03f);
    float t = __fdiv_rn(np, q);
    return (fabsf(x) < 4.0e-4f) ? x : t;
}
__device__ __forceinline__ float xla_sigmoid(float x) {
    float t = xla_tanh(__fmul_rn(x, 0.5f));
    return __fadd_rn(0.5f, __fmul_rn(0.5f, t));
}

// ---------- cluster helpers ----------
__device__ __forceinline__ unsigned ctarank() {
    unsigned r; asm("mov.u32 %0, %%cluster_ctarank;" : "=r"(r)); return r;
}
__device__ __forceinline__ unsigned smem_addr_u32(const void* p) {
    return (unsigned)__cvta_generic_to_shared(p);
}
__device__ __forceinline__ void st_cluster_f32(unsigned saddr, unsigned rank, float v) {
    asm volatile(
        "{\n\t.reg .b32 ra;\n\t"
        "mapa.shared::cluster.u32 ra, %0, %1;\n\t"
        "st.shared::cluster.f32 [ra], %2;\n\t}"
        :: "r"(saddr), "r"(rank), "f"(v) : "memory");
}
#define CLUSTER_SYNC() do { \
    asm volatile("barrier.cluster.arrive.aligned;" ::: "memory"); \
    asm volatile("barrier.cluster.wait.aligned;" ::: "memory"); } while (0)

// ---------- dtype probe ----------
__global__ void k_probe(const void* emb, const void* ph) {
    __shared__ int cnt;
    __shared__ int i64ok;
    int t = threadIdx.x;
    if (t == 0) { cnt = 0; i64ok = 1; }
    __syncthreads();
    unsigned short u = ((const unsigned short*)emb)[2 * t];
    int e = (u >> 7) & 0xFF;
    int plaus = (u == 0) || (e >= 90 && e <= 134);
    atomicAdd(&cnt, plaus);
    if (t < 64) {
        int lo = ((const int*)ph)[2 * t];
        int hi = ((const int*)ph)[2 * t + 1];
        if (!(hi == 0 && lo >= 0 && lo < 512)) atomicAnd(&i64ok, 0);
    }
    __syncthreads();
    if (t == 0) {
        int f = 0;
        if (cnt >= 128) f |= 1;
        if (i64ok)      f |= 2;
        g_dtflag = f;
    }
}

// ---------- conversion + transpose, single kernel ----------
__device__ __forceinline__ float cvt_load(const void* src, int i) {
    if (g_dtflag & 1) return __bfloat162float(((const __nv_bfloat16*)src)[i]);
    return ((const float*)src)[i];
}
__global__ void k_cvt_all(const void* mel, const void* emb,
                          const void* w0, const void* w1, const void* w2, const void* w3,
                          const void* b0, const void* b1, const void* b2, const void* b3,
                          const void* wfc, const void* bfc, const void* ph) {
    int i = blockIdx.x * 256 + threadIdx.x;
    int seg = blockIdx.y;
    switch (seg) {
        case 0: if (i < NB * TMEL * NMELS) s_mel[i] = cvt_load(mel, i); break;
        case 1: if (i < 512 * DIMH) s_emb[i] = cvt_load(emb, i); break;
        case 2: if (i < 768 * DIMH) {                      // Wih_f -> WihT[:, 0:768]
            int j = i >> 8, k = i & 255;
            g_WihT[k * 1536 + j] = cvt_load(w0, i);
        } break;
        case 3: if (i < 768 * DIMH) {                      // Whh_f -> WhhT dir0
            int j = i >> 8, k = i & 255;
            g_WhhT[k * 768 + j] = cvt_load(w1, i);
        } break;
        case 4: if (i < 768 * DIMH) {                      // Wih_b -> WihT[:, 768:]
            int j = i >> 8, k = i & 255;
            g_WihT[k * 1536 + 768 + j] = cvt_load(w2, i);
        } break;
        case 5: if (i < 768 * DIMH) {                      // Whh_b -> WhhT dir1
            int j = i >> 8, k = i & 255;
            g_WhhT[(256 + k) * 768 + j] = cvt_load(w3, i);
        } break;
        case 6: if (i < 768) s_bih_f[i] = cvt_load(b0, i); break;
        case 7: if (i < 768) s_bhh_f[i] = cvt_load(b1, i); break;
        case 8: if (i < 768) s_bih_b[i] = cvt_load(b2, i); break;
        case 9: if (i < 768) s_bhh_b[i] = cvt_load(b3, i); break;
        case 10: if (i < NMELS * 512) {                    // Wfc[80][512] -> WfcT[512][80]
            int m = i >> 9, d = i & 511;
            g_WfcT[d * NMELS + m] = cvt_load(wfc, i);
        } break;
        case 11: if (i < NMELS) s_bfc[i] = cvt_load(bfc, i); break;
        default: if (i < NB * TPH) {
            int v;
            if (g_dtflag & 2) v = (int)((const long long*)ph)[i];
            else              v = ((const int*)ph)[i];
            s_ph[i] = v & 511;
        } break;
    }
}

__device__ __forceinline__ void store_out(void* out, long long idx, long long osz, float v) {
    if (idx < 0 || idx >= osz) return;
    ((float*)out)[idx] = v;
}
__global__ void k_zero4(void* out, long long n4) {
    long long i = (long long)blockIdx.x * blockDim.x + threadIdx.x;
    if (i < n4) ((float4*)out)[i] = make_float4(0.f, 0.f, 0.f, 0.f);
}

// ---------- xproj: 8 phonemes x half-j per block; grid (2, 64) ----------
__global__ void __launch_bounds__(256) k_embproj() {
    int jh = blockIdx.x;          // 0/1 -> j offset 0 / 768
    int p0 = blockIdx.y * 8;
    int j = threadIdx.x;          // 0..255 -> 3 j-slices
    __shared__ float s_e[8][DIMH];
    for (int idx = j; idx < 8 * DIMH; idx += 256) s_e[idx >> 8][idx & 255] = s_emb[(p0 + (idx >> 8)) * DIMH + (idx & 255)];
    __syncthreads();
    float acc[3][8];
#pragma unroll
    for (int i = 0; i < 3; i++)
#pragma unroll
        for (int p = 0; p < 8; p++) acc[i][p] = 0.f;
    for (int k = 0; k < DIMH; k++) {
        const float* w = g_WihT + k * 1536 + jh * 768;
        float wv[3];
#pragma unroll
        for (int i = 0; i < 3; i++) wv[i] = w[i * 256 + j];
#pragma unroll
        for (int p = 0; p < 8; p++) {
            float e = s_e[p][k];
#pragma unroll
            for (int i = 0; i < 3; i++) acc[i][p] = fmaf(wv[i], e, acc[i][p]);
        }
    }
#pragma unroll
    for (int i = 0; i < 3; i++) {
        int jj = jh * 768 + i * 256 + j;
        float b = (jj < 768) ? s_bih_f[jj] : s_bih_b[jj - 768];
#pragma unroll
        for (int p = 0; p < 8; p++)
            g_xproj[(p0 + p) * 1536 + jj] = __fadd_rn(acc[i][p], b);
    }
}

// ---------- GRU: 4-CTA cluster; half Whh in regs, half in SMEM ----------
#define GRU_SMEM_BYTES ((128*192 + 2*256 + 192 + 192) * 4)
__global__ void __launch_bounds__(192, 1) __cluster_dims__(4, 1, 1) k_gru_cl() {
    extern __shared__ float smf[];
    float* w  = smf;                 // k 128..255 slice: 98304 B
    float* hb = smf + 128 * 192;     // [2][256]
    float* sa = hb + 512;            // [192]
    float* sx = sa + 192;            // [192]
    int tid = threadIdx.x;
    unsigned rk = ctarank();
    int cid = blockIdx.x >> 2;
    int dir = cid >> 4, b = cid & 15;
    int l = tid & 63;
    int row = (tid / 64) * 256 + (int)rk * 64 + l;
    int hd = (int)rk * 64 + l;

    const float* Wt = g_WhhT + (size_t)dir * DIMH * 768;
    // k = 0..127 in registers
    float4 wr[32];
#pragma unroll
    for (int q = 0; q < 32; q++) {
        wr[q].x = Wt[(4 * q + 0) * 768 + row];
        wr[q].y = Wt[(4 * q + 1) * 768 + row];
        wr[q].z = Wt[(4 * q + 2) * 768 + row];
        wr[q].w = Wt[(4 * q + 3) * 768 + row];
    }
    // k = 128..255 in SMEM
    for (int q = 0; q < 32; q++) {
        float4 wv;
        wv.x = Wt[(128 + 4 * q + 0) * 768 + row];
        wv.y = Wt[(128 + 4 * q + 1) * 768 + row];
        wv.z = Wt[(128 + 4 * q + 2) * 768 + row];
        wv.w = Wt[(128 + 4 * q + 3) * 768 + row];
        ((float4*)w)[q * 192 + tid] = wv;
    }
    for (int k = tid; k < 512; k += 192) hb[k] = 0.f;

    const float* bhh = dir ? s_bhh_b : s_bhh_f;
    float br = 0.f, bz = 0.f, bn = 0.f;
    if (tid < 64) { br = bhh[hd]; bz = bhh[256 + hd]; bn = bhh[512 + hd]; }
    const int* phb = s_ph + b * TPH;
    float* Hout = g_H + ((size_t)(dir * NB + b)) * TPH * DIMH;
    unsigned hb_base = smem_addr_u32(hb);
    __syncthreads();
    CLUSTER_SYNC();

    for (int s = 0; s < TPH; s++) {
        int t = dir ? (TPH - 1 - s) : s;
        int pv = phb[t] & 511;
        float xg = g_xproj[(size_t)pv * 1536 + dir * 768 + row];
        const float* hc = hb + (s & 1) * 256;
        float a = 0.f;
#pragma unroll
        for (int q = 0; q < 32; q++) {
            float4 hv = ((const float4*)hc)[q];
            a = fmaf(wr[q].x, hv.x, a);
            a = fmaf(wr[q].y, hv.y, a);
            a = fmaf(wr[q].z, hv.z, a);
            a = fmaf(wr[q].w, hv.w, a);
        }
#pragma unroll 8
        for (int q = 0; q < 32; q++) {
            float4 wv = ((const float4*)w)[q * 192 + tid];
            float4 hv = ((const float4*)hc)[32 + q];
            a = fmaf(wv.x, hv.x, a);
            a = fmaf(wv.y, hv.y, a);
            a = fmaf(wv.z, hv.z, a);
            a = fmaf(wv.w, hv.w, a);
        }
        sa[tid] = a;
        sx[tid] = xg;
        __syncthreads();
        if (tid < 64) {
            float hr = __fadd_rn(sa[l], br);
            float hz = __fadd_rn(sa[64 + l], bz);
            float hn = __fadd_rn(sa[128 + l], bn);
            float r = xla_sigmoid(__fadd_rn(sx[l], hr));
            float z = xla_sigmoid(__fadd_rn(sx[64 + l], hz));
            float n = xla_tanh(__fadd_rn(sx[128 + l], __fmul_rn(r, hn)));
            float hprev = hc[hd];
            float hnew = __fadd_rn(__fmul_rn(__fsub_rn(1.0f, z), n), __fmul_rn(z, hprev));
            Hout[(size_t)t * DIMH + hd] = hnew;
            unsigned dst = hb_base + (unsigned)((((s + 1) & 1) * 256 + hd) * 4);
            st_cluster_f32(dst, 0, hnew);
            st_cluster_f32(dst, 1, hnew);
            st_cluster_f32(dst, 2, hnew);
            st_cluster_f32(dst, 3, hnew);
        }
        CLUSTER_SYNC();
    }
}

// ---------- fc: 8 phonemes per block ----------
__global__ void __launch_bounds__(128) k_fc() {
    int p0 = blockIdx.x * 8;
    int b = blockIdx.y;
    int m = threadIdx.x;      // 0..127
    __shared__ float hcat[8][512];
    __shared__ float sq[8][NMELS];
    for (int idx = m; idx < 8 * 512; idx += 128) {
        int i = idx >> 9, d = idx & 511;
        float v;
        if (d < DIMH) v = g_H[((size_t)b * TPH + p0 + i) * DIMH + d];
        else          v = g_H[((size_t)(NB + b) * TPH + p0 + i) * DIMH + (d - DIMH)];
        hcat[i][d] = v;
    }
    __syncthreads();
    if (m < NMELS) {
        float acc[8];
#pragma unroll
        for (int i = 0; i < 8; i++) acc[i] = 0.f;
        for (int d = 0; d < 512; d++) {
            float wv = g_WfcT[d * NMELS + m];
#pragma unroll
            for (int i = 0; i < 8; i++) acc[i] = fmaf(wv, hcat[i][d], acc[i]);
        }
        float bb = s_bfc[m];
#pragma unroll
        for (int i = 0; i < 8; i++) {
            float o = __fadd_rn(acc[i], bb);
            g_xenc[((size_t)b * TPH + p0 + i) * NMELS + m] = o;
            sq[i][m] = __fmul_rn(o, o);
        }
    }
    __syncthreads();
    if (m < 8) {
        float s = 0.f;
        for (int k = 0; k < NMELS; k++) s = __fadd_rn(s, sq[m][k]);
        g_musq[b * TPH + p0 + m] = __fmul_rn(-0.5f, s);
    }
}

__global__ void k_ysq() {
    int i = blockIdx.x * blockDim.x + threadIdx.x;
    if (i >= NB * TMEL) return;
    const float* r = s_mel + (size_t)i * NMELS;
    float s = 0.f;
    for (int k = 0; k < NMELS; k++) s = __fadd_rn(s, __fmul_rn(r[k], r[k]));
    g_ysq[i] = __fmul_rn(-0.5f, s);
}

// ---------- V gemm ----------
__global__ void __launch_bounds__(256) k_vgemm() {
    int b = blockIdx.z;
    int y0 = blockIdx.y * 64, p0 = blockIdx.x * 64;
    int t = threadIdx.x;
    int ty = t >> 4, tp = t & 15;
    __shared__ __align__(16) float sm[NMELS][64];
    __shared__ __align__(16) float sx[NMELS][64];
    for (int idx = t; idx < 64 * NMELS; idx += 256) {
        int i = idx / NMELS, k = idx % NMELS;
        sm[k][i] = s_mel[((size_t)b * TMEL + y0 + i) * NMELS + k];
        sx[k][i] = g_xenc[((size_t)b * TPH + p0 + i) * NMELS + k];
    }
    __syncthreads();
    float acc[4][4];
#pragma unroll
    for (int i = 0; i < 4; i++)
#pragma unroll
        for (int jj = 0; jj < 4; jj++) acc[i][jj] = 0.f;
    for (int k = 0; k < NMELS; k++) {
        float4 a = ((const float4*)&sm[k][0])[ty];
        float4 bb = ((const float4*)&sx[k][0])[tp];
        float av[4] = {a.x, a.y, a.z, a.w};
        float bv[4] = {bb.x, bb.y, bb.z, bb.w};
#pragma unroll
        for (int i = 0; i < 4; i++)
#pragma unroll
            for (int jj = 0; jj < 4; jj++) acc[i][jj] = fmaf(av[i], bv[jj], acc[i][jj]);
    }
    float4 mu = ((const float4*)(g_musq + b * TPH + p0))[tp];
    float muv[4] = {mu.x, mu.y, mu.z, mu.w};
#pragma unroll
    for (int i = 0; i < 4; i++) {
        int y = y0 + ty * 4 + i;
        float ys = g_ysq[b * TMEL + y];
        float4 o;
#pragma unroll
        for (int jj = 0; jj < 4; jj++) {
            float v1 = __fadd_rn(ys, acc[i][jj]);
            float v2 = __fadd_rn(v1, muv[jj]);
            float vv = __fadd_rn(v2, VCONST);
            if (jj == 0) o.x = vv; else if (jj == 1) o.y = vv;
            else if (jj == 2) o.z = vv; else o.w = vv;
        }
        ((float4*)(g_V + ((size_t)b * TMEL + y) * TPH + p0))[tp] = o;
    }
}

// ---------- DP forward ----------
__global__ void __launch_bounds__(TPH) k_dp() {
    int b = blockIdx.x, x = threadIdx.x;
    __shared__ float s_c[2][TPH];
    float carry = (x == 0) ? 0.f : NEGC;
    const float* Vb = g_V + (size_t)b * TMEL * TPH;
    float v0 = Vb[x];
    float v1 = Vb[TPH + x];
    for (int y = 0; y < TMEL; y++) {
        float vf = (y + 2 < TMEL) ? Vb[(size_t)(y + 2) * TPH + x] : 0.f;
        s_c[y & 1][x] = carry;
        __syncthreads();
        float sh = (x > 0) ? s_c[y & 1][x - 1] : NEGC;
        unsigned bal = __ballot_sync(0xffffffffu, sh > carry);
        if ((x & 31) == 0) g_diag[(b * TMEL + y) * 16 + (x >> 5)] = bal;
        carry = __fadd_rn(v0, fmaxf(carry, sh));
        v0 = v1;
        v1 = vf;
    }
}

__global__ void k_backtrack() {
    __shared__ unsigned s_d[256 * 16];
    __shared__ int s_idx;
    int b = blockIdx.x, t = threadIdx.x;
    if (t == 0) s_idx = TPH - 1;
    for (int chunk = 7; chunk >= 0; chunk--) {
        __syncthreads();
        const unsigned* src = g_diag + ((size_t)b * TMEL + chunk * 256) * 16;
        for (int i = t; i < 256 * 16; i += blockDim.x) s_d[i] = src[i];
        __syncthreads();
        if (t == 0) {
            int idx = s_idx;
            for (int yy = 255; yy >= 0; yy--) {
                g_path[b * TMEL + chunk * 256 + yy] = idx;
                int bit = (s_d[yy * 16 + ((idx >> 5) & 15)] >> (idx & 31)) & 1;
                idx -= bit;
                if (idx < 0) idx = 0;
            }
            s_idx = idx;
        }
    }
}

__global__ void k_finish(void* out, long long osz) {
    int y = blockIdx.x, b = blockIdx.y;
    int m = threadIdx.x;
    int p = g_path[b * TMEL + y] & 511;
    if (m == 0) {
        store_out(out, (long long)(b * TPH + p) * TMEL + y, osz, 1.f);
    }
    float sq = 0.f;
    if (m < NMELS) {
        float e = g_xenc[((size_t)b * TPH + p) * NMELS + m];
        store_out(out, (long long)ATTN_N + (long long)(b * TMEL + y) * NMELS + m, osz, e);
        float d = e - s_mel[((size_t)b * TMEL + y) * NMELS + m];
        sq = d * d;
    }
#pragma unroll
    for (int off = 16; off > 0; off >>= 1) sq += __shfl_down_sync(0xffffffffu, sq, off);
    __shared__ float s_w[3];
    if ((m & 31) == 0) s_w[m >> 5] = sq;
    __syncthreads();
    if (m == 0) g_partial[b * TMEL + y] = s_w[0] + s_w[1] + s_w[2];
}

__global__ void k_loss(void* out, long long osz) {
    __shared__ double s[512];
    int t = threadIdx.x;
    double acc = 0.0;
    for (int i = 0; i < 64; i++) acc += (double)g_partial[t * 64 + i];
    s[t] = acc;
    __syncthreads();
    for (int off = 256; off > 0; off >>= 1) {
        if (t < off) s[t] += s[t + off];
        __syncthreads();
    }
    if (t == 0) store_out(out, (long long)ATTN_N + (long long)EXP_N, osz,
                          (float)(s[0] / 32768.0 / 80.0));
}

// ---------- host ----------
static void dbg_sync(const char* name) {
    cudaStreamCaptureStatus st = cudaStreamCaptureStatusNone;
    cudaStreamIsCapturing(0, &st);
    if (st != cudaStreamCaptureStatusNone) return;
    cudaError_t e = cudaDeviceSynchronize();
    fprintf(stderr, "[ck] %s: %s\n", name, cudaGetErrorName(e));
    fflush(stderr);
}

extern "C" void kernel_launch(void* const* d_in, const int* in_sizes, int n_in,
                              void* d_out, int out_size) {
    const void* ph = 0;
    const void *mel = 0, *emb = 0, *Wfc = 0, *bfc = 0;
    const void* W196[4] = {0, 0, 0, 0};
    const void* b768[4] = {0, 0, 0, 0};
    int n196 = 0, n768 = 0;
    for (int i = 0; i < n_in; i++) {
        int sz = in_sizes[i];
        if (sz == NB * TPH && !ph)                ph  = d_in[i];
        else if (sz == NB * TMEL * NMELS && !mel) mel = d_in[i];
        else if (sz == 512 * DIMH && !emb)        emb = d_in[i];
        else if (sz == 768 * DIMH && n196 < 4)    W196[n196++] = d_in[i];
        else if (sz == 768 && n768 < 4)           b768[n768++] = d_in[i];
        else if (sz == NMELS * 512 && !Wfc)       Wfc = d_in[i];
        else if (sz == NMELS && !bfc)             bfc = d_in[i];
    }
    long long osz = (long long)out_size;

    // launch order: #4 = k_gru_cl (gets profiled)
    k_probe<<<1, 256>>>(emb, ph);                                          // 1
    k_cvt_all<<<dim3((NB * TMEL * NMELS + 255) / 256, 13), 256>>>(         // 2
        mel, emb, W196[0], W196[1], W196[2], W196[3],
        b768[0], b768[1], b768[2], b768[3], Wfc, bfc, ph);
    k_embproj<<<dim3(2, 64), 256>>>();                                     // 3

    cudaFuncSetAttribute(k_gru_cl, cudaFuncAttributeMaxDynamicSharedMemorySize,
                         GRU_SMEM_BYTES);
    k_gru_cl<<<128, 192, GRU_SMEM_BYTES>>>();                              // 4 <- profiled
    dbg_sync("gru");

    long long zn = osz < (long long)ATTN_N ? osz : (long long)ATTN_N;
    k_zero4<<<(int)((zn / 4 + 255) / 256), 256>>>(d_out, zn / 4);          // 5
    k_fc<<<dim3(TPH / 8, NB), 128>>>();                                    // 6
    k_ysq<<<(NB * TMEL + 255) / 256, 256>>>();                             // 7
    k_vgemm<<<dim3(TPH / 64, TMEL / 64, NB), 256>>>();                     // 8
    k_dp<<<NB, TPH>>>();                                                   // 9
    k_backtrack<<<NB, 256>>>();                                            // 10
    k_finish<<<dim3(TMEL, NB), 96>>>(d_out, osz);                          // 11
    k_loss<<<1, 512>>>(d_out, osz);                                        // 12
    dbg_sync("end");
}